// round 1
// baseline (speedup 1.0000x reference)
#include <cuda_runtime.h>
#include <cstddef>

#define BATCH   64
#define NCAPS   32
#define NROUTES 2048
#define INDIM   16
#define OUTDIM  32
#define NITERS  3
#define THREADS 512

// SMEM layout (floats):
//   sp[1024][33]   : priors for routes 1024..2047 (row r-1024), 33-stride pad -> conflict-free
//   Vsh[32]        : cumulative output vector (sum of v_j)
//   sred[32]       : reduced s vector
//   wred[32]       : per-warp scalar reduction scratch
//   wvec[16*32]    : per-warp partial s vectors
//   scal[8]        : [0]=block max, [1]=block Z
#define SP_STRIDE 33
#define OFF_SP    0
#define OFF_VSH   (1024 * SP_STRIDE)
#define OFF_SRED  (OFF_VSH + 32)
#define OFF_WRED  (OFF_SRED + 32)
#define OFF_WVEC  (OFF_WRED + 32)
#define OFF_SCAL  (OFF_WVEC + 16 * 32)
#define SMEM_FLOATS (OFF_SCAL + 8)
#define SMEM_BYTES  (SMEM_FLOATS * 4)

__device__ __forceinline__ void compute_route(const float* __restrict__ x,
                                              const float* __restrict__ W,
                                              int b, int c, int r,
                                              float* __restrict__ acc)
{
    const float4* xr = reinterpret_cast<const float4*>(x + ((size_t)b * NROUTES + r) * INDIM);
    const float4* wr = reinterpret_cast<const float4*>(W + (((size_t)c * NROUTES + r) * INDIM) * OUTDIM);

    float xv[INDIM];
#pragma unroll
    for (int q = 0; q < 4; q++) {
        float4 v = xr[q];
        xv[4 * q + 0] = v.x; xv[4 * q + 1] = v.y;
        xv[4 * q + 2] = v.z; xv[4 * q + 3] = v.w;
    }
#pragma unroll
    for (int o = 0; o < OUTDIM; o++) acc[o] = 0.f;

#pragma unroll
    for (int i = 0; i < INDIM; i++) {
        float xi = xv[i];
#pragma unroll
        for (int o4 = 0; o4 < OUTDIM / 4; o4++) {
            float4 w = wr[i * (OUTDIM / 4) + o4];
            acc[o4 * 4 + 0] += xi * w.x;
            acc[o4 * 4 + 1] += xi * w.y;
            acc[o4 * 4 + 2] += xi * w.z;
            acc[o4 * 4 + 3] += xi * w.w;
        }
    }
}

__global__ void __launch_bounds__(THREADS, 1)
caps_route_kernel(const float* __restrict__ x,
                  const float* __restrict__ W,
                  float* __restrict__ out)
{
    extern __shared__ float sm[];
    float* sp   = sm + OFF_SP;
    float* Vsh  = sm + OFF_VSH;
    float* sred = sm + OFF_SRED;
    float* wred = sm + OFF_WRED;
    float* wvec = sm + OFF_WVEC;
    float* scal = sm + OFF_SCAL;

    const int t    = threadIdx.x;
    const int lane = t & 31;
    const int wid  = t >> 5;
    const int b    = blockIdx.x & (BATCH - 1);
    const int c    = blockIdx.x >> 6;

    if (t < 32) Vsh[t] = 0.f;

    // ---------------- Phase 1: priors (computed exactly once) ----------------
    // Thread t owns routes: t (regs), t+512 (regs), t+1024 (smem), t+1536 (smem)
    {
        float acc[OUTDIM];
        compute_route(x, W, b, c, t + 1024, acc);
        float* row = sp + (size_t)t * SP_STRIDE;
#pragma unroll
        for (int o = 0; o < OUTDIM; o++) row[o] = acc[o];

        compute_route(x, W, b, c, t + 1536, acc);
        float* row2 = sp + (size_t)(512 + t) * SP_STRIDE;
#pragma unroll
        for (int o = 0; o < OUTDIM; o++) row2[o] = acc[o];
    }
    float accA[OUTDIM], accB[OUTDIM];
    compute_route(x, W, b, c, t, accA);
    compute_route(x, W, b, c, t + 512, accB);

    const float* rowC = sp + (size_t)t * SP_STRIDE;
    const float* rowD = sp + (size_t)(512 + t) * SP_STRIDE;

    __syncthreads();

    // ---------------- Phase 2: dynamic routing ----------------
    for (int it = 0; it < NITERS; it++) {
        float p0, p1, p2, p3;
        if (it == 0) {
            p0 = p1 = p2 = p3 = 1.0f / (float)NROUTES;
        } else {
            // logits = p_r . V   (B_k[n] == p_n . sum_j v_j)
            float l0 = 0.f, l1 = 0.f, l2 = 0.f, l3 = 0.f;
#pragma unroll
            for (int o = 0; o < OUTDIM; o++) {
                float v = Vsh[o];
                l0 += accA[o] * v;
                l1 += accB[o] * v;
                l2 += rowC[o] * v;
                l3 += rowD[o] * v;
            }
            // block max
            float m = fmaxf(fmaxf(l0, l1), fmaxf(l2, l3));
#pragma unroll
            for (int s = 16; s; s >>= 1) m = fmaxf(m, __shfl_xor_sync(0xffffffffu, m, s));
            if (lane == 0) wred[wid] = m;
            __syncthreads();
            if (wid == 0) {
                float mm = (lane < 16) ? wred[lane] : -3.402823e38f;
#pragma unroll
                for (int s = 16; s; s >>= 1) mm = fmaxf(mm, __shfl_xor_sync(0xffffffffu, mm, s));
                if (lane == 0) scal[0] = mm;
            }
            __syncthreads();
            const float bmax = scal[0];

            float e0 = __expf(l0 - bmax);
            float e1 = __expf(l1 - bmax);
            float e2 = __expf(l2 - bmax);
            float e3 = __expf(l3 - bmax);
            float zs = e0 + e1 + e2 + e3;
#pragma unroll
            for (int s = 16; s; s >>= 1) zs += __shfl_xor_sync(0xffffffffu, zs, s);
            if (lane == 0) wred[wid] = zs;
            __syncthreads();
            if (wid == 0) {
                float zz = (lane < 16) ? wred[lane] : 0.f;
#pragma unroll
                for (int s = 16; s; s >>= 1) zz += __shfl_xor_sync(0xffffffffu, zz, s);
                if (lane == 0) scal[1] = zz;
            }
            __syncthreads();
            const float invZ = 1.0f / scal[1];
            p0 = e0 * invZ; p1 = e1 * invZ; p2 = e2 * invZ; p3 = e3 * invZ;
        }

        // s = sum_n probs_n * p_n  (32-vector reduced over 2048 routes, deterministic tree)
        float ps[OUTDIM];
#pragma unroll
        for (int o = 0; o < OUTDIM; o++)
            ps[o] = p0 * accA[o] + p1 * accB[o] + p2 * rowC[o] + p3 * rowD[o];
#pragma unroll
        for (int s = 16; s; s >>= 1) {
#pragma unroll
            for (int o = 0; o < OUTDIM; o++)
                ps[o] += __shfl_xor_sync(0xffffffffu, ps[o], s);
        }
        if (lane == 0) {
#pragma unroll
            for (int o = 0; o < OUTDIM; o++) wvec[wid * 32 + o] = ps[o];
        }
        __syncthreads();
        if (t < 32) {
            float sv = 0.f;
#pragma unroll
            for (int w = 0; w < 16; w++) sv += wvec[w * 32 + t];
            sred[t] = sv;
        }
        __syncthreads();

        // squash + accumulate V; final-iteration writes output
        if (t < 32) {
            float nr = 0.f;
#pragma unroll
            for (int o = 0; o < OUTDIM; o++) { float sv = sred[o]; nr += sv * sv; }
            float scale = (nr / (1.0f + nr)) * rsqrtf(nr);
            float v = scale * sred[t];
            Vsh[t] += v;
            if (it == NITERS - 1)
                out[((size_t)b * NCAPS + c) * OUTDIM + t] = v;
        }
        __syncthreads();
    }
}

extern "C" void kernel_launch(void* const* d_in, const int* in_sizes, int n_in,
                              void* d_out, int out_size)
{
    const float* x = (const float*)d_in[0];         // [64, 2048, 16]
    const float* W = (const float*)d_in[1];         // [32, 2048, 16, 32]
    float* out = (float*)d_out;                     // [64, 32, 32]

    cudaFuncSetAttribute(caps_route_kernel,
                         cudaFuncAttributeMaxDynamicSharedMemorySize, SMEM_BYTES);

    dim3 grid(BATCH * NCAPS);   // bid = c*64 + b  (c-major -> same-c CTAs co-resident for L2 W reuse)
    caps_route_kernel<<<grid, THREADS, SMEM_BYTES>>>(x, W, out);
}

// round 2
// speedup vs baseline: 2.2839x; 2.2839x over previous
#include <cuda_runtime.h>
#include <cstddef>

#define BATCH   64
#define NCAPS   32
#define NROUTES 2048
#define INDIM   16
#define OUTDIM  32
#define NITERS  3
#define THREADS 512

// SMEM layout (floats):
//   sp[1024][33]   : priors for one half of the routes (33-stride pad -> conflict-free)
//   Vsh[32], sred[32], wred[32], wvec[16*32], scal[8]
#define SP_STRIDE 33
#define OFF_SP    0
#define OFF_VSH   (1024 * SP_STRIDE)
#define OFF_SRED  (OFF_VSH + 32)
#define OFF_WRED  (OFF_SRED + 32)
#define OFF_WVEC  (OFF_WRED + 32)
#define OFF_SCAL  (OFF_WVEC + 16 * 32)
#define SMEM_FLOATS (OFF_SCAL + 8)
#define SMEM_BYTES  (SMEM_FLOATS * 4)

// Warp-cooperative prior: lane `lane` computes output column `lane` of route r.
// W reads are coalesced LDG.32 (one 128B line per i), x reads are broadcast float4.
__device__ __forceinline__ float route_lane(const float* __restrict__ x,
                                            const float* __restrict__ W,
                                            int b, int c, int r, int lane)
{
    const float4* xr4 = reinterpret_cast<const float4*>(x + ((size_t)b * NROUTES + r) * INDIM);
    const float* Wr = W + ((size_t)c * NROUTES + r) * (INDIM * OUTDIM) + lane;
    float acc = 0.f;
#pragma unroll
    for (int q = 0; q < 4; q++) {
        float4 xq = __ldg(&xr4[q]);
        acc = fmaf(xq.x, __ldg(Wr + (q * 4 + 0) * OUTDIM), acc);
        acc = fmaf(xq.y, __ldg(Wr + (q * 4 + 1) * OUTDIM), acc);
        acc = fmaf(xq.z, __ldg(Wr + (q * 4 + 2) * OUTDIM), acc);
        acc = fmaf(xq.w, __ldg(Wr + (q * 4 + 3) * OUTDIM), acc);
    }
    return acc;
}

__global__ void __launch_bounds__(THREADS, 1)
caps_route_kernel(const float* __restrict__ x,
                  const float* __restrict__ W,
                  float* __restrict__ out)
{
    extern __shared__ float sm[];
    float* sp   = sm + OFF_SP;
    float* Vsh  = sm + OFF_VSH;
    float* sred = sm + OFF_SRED;
    float* wred = sm + OFF_WRED;
    float* wvec = sm + OFF_WVEC;
    float* scal = sm + OFF_SCAL;

    const int t    = threadIdx.x;
    const int lane = t & 31;
    const int wid  = t >> 5;
    const int b    = blockIdx.x & (BATCH - 1);
    const int c    = blockIdx.x >> 6;

    if (t < 32) Vsh[t] = 0.f;

    // ---------------- Phase 1a: routes 0..1023 (warp w -> routes w*64..w*64+63) ----------------
    {
        const int base = wid * 64;
#pragma unroll 2
        for (int j = 0; j < 64; j += 2) {
            int r0 = base + j, r1 = base + j + 1;
            float a0 = route_lane(x, W, b, c, r0, lane);
            float a1 = route_lane(x, W, b, c, r1, lane);
            sp[(size_t)r0 * SP_STRIDE + lane] = a0;
            sp[(size_t)r1 * SP_STRIDE + lane] = a1;
        }
    }
    __syncthreads();

    // Each thread pulls its two register rows (routes t and t+512) out of SMEM.
    float accA[OUTDIM], accB[OUTDIM];
    {
        const float* rA = sp + (size_t)t * SP_STRIDE;
        const float* rB = sp + (size_t)(512 + t) * SP_STRIDE;
#pragma unroll
        for (int o = 0; o < OUTDIM; o++) { accA[o] = rA[o]; accB[o] = rB[o]; }
    }
    __syncthreads();

    // ---------------- Phase 1b: routes 1024..2047 overwrite SMEM ----------------
    {
        const int base = wid * 64;
#pragma unroll 2
        for (int j = 0; j < 64; j += 2) {
            int r0 = 1024 + base + j, r1 = 1024 + base + j + 1;
            float a0 = route_lane(x, W, b, c, r0, lane);
            float a1 = route_lane(x, W, b, c, r1, lane);
            sp[(size_t)(r0 - 1024) * SP_STRIDE + lane] = a0;
            sp[(size_t)(r1 - 1024) * SP_STRIDE + lane] = a1;
        }
    }
    __syncthreads();

    const float* rowC = sp + (size_t)t * SP_STRIDE;          // route 1024+t
    const float* rowD = sp + (size_t)(512 + t) * SP_STRIDE;  // route 1536+t

    // ---------------- Phase 2: dynamic routing (B_k[n] == p_n . sum_j v_j) ----------------
    for (int it = 0; it < NITERS; it++) {
        float p0, p1, p2, p3;
        if (it == 0) {
            p0 = p1 = p2 = p3 = 1.0f / (float)NROUTES;
        } else {
            float l0 = 0.f, l1 = 0.f, l2 = 0.f, l3 = 0.f;
#pragma unroll
            for (int o = 0; o < OUTDIM; o++) {
                float v = Vsh[o];
                l0 += accA[o] * v;
                l1 += accB[o] * v;
                l2 += rowC[o] * v;
                l3 += rowD[o] * v;
            }
            float m = fmaxf(fmaxf(l0, l1), fmaxf(l2, l3));
#pragma unroll
            for (int s = 16; s; s >>= 1) m = fmaxf(m, __shfl_xor_sync(0xffffffffu, m, s));
            if (lane == 0) wred[wid] = m;
            __syncthreads();
            if (wid == 0) {
                float mm = (lane < 16) ? wred[lane] : -3.402823e38f;
#pragma unroll
                for (int s = 16; s; s >>= 1) mm = fmaxf(mm, __shfl_xor_sync(0xffffffffu, mm, s));
                if (lane == 0) scal[0] = mm;
            }
            __syncthreads();
            const float bmax = scal[0];

            float e0 = __expf(l0 - bmax);
            float e1 = __expf(l1 - bmax);
            float e2 = __expf(l2 - bmax);
            float e3 = __expf(l3 - bmax);
            float zs = e0 + e1 + e2 + e3;
#pragma unroll
            for (int s = 16; s; s >>= 1) zs += __shfl_xor_sync(0xffffffffu, zs, s);
            if (lane == 0) wred[wid] = zs;
            __syncthreads();
            if (wid == 0) {
                float zz = (lane < 16) ? wred[lane] : 0.f;
#pragma unroll
                for (int s = 16; s; s >>= 1) zz += __shfl_xor_sync(0xffffffffu, zz, s);
                if (lane == 0) scal[1] = zz;
            }
            __syncthreads();
            const float invZ = 1.0f / scal[1];
            p0 = e0 * invZ; p1 = e1 * invZ; p2 = e2 * invZ; p3 = e3 * invZ;
        }

        // s = sum_n probs_n * p_n  (deterministic tree reduction)
        float ps[OUTDIM];
#pragma unroll
        for (int o = 0; o < OUTDIM; o++)
            ps[o] = p0 * accA[o] + p1 * accB[o] + p2 * rowC[o] + p3 * rowD[o];
#pragma unroll
        for (int s = 16; s; s >>= 1) {
#pragma unroll
            for (int o = 0; o < OUTDIM; o++)
                ps[o] += __shfl_xor_sync(0xffffffffu, ps[o], s);
        }
        if (lane == 0) {
#pragma unroll
            for (int o = 0; o < OUTDIM; o++) wvec[wid * 32 + o] = ps[o];
        }
        __syncthreads();
        if (t < 32) {
            float sv = 0.f;
#pragma unroll
            for (int w = 0; w < 16; w++) sv += wvec[w * 32 + t];
            sred[t] = sv;
        }
        __syncthreads();

        if (t < 32) {
            float nr = 0.f;
#pragma unroll
            for (int o = 0; o < OUTDIM; o++) { float sv = sred[o]; nr += sv * sv; }
            float scale = (nr / (1.0f + nr)) * rsqrtf(nr);
            float v = scale * sred[t];
            Vsh[t] += v;
            if (it == NITERS - 1)
                out[((size_t)b * NCAPS + c) * OUTDIM + t] = v;
        }
        __syncthreads();
    }
}

extern "C" void kernel_launch(void* const* d_in, const int* in_sizes, int n_in,
                              void* d_out, int out_size)
{
    const float* x = (const float*)d_in[0];         // [64, 2048, 16]
    const float* W = (const float*)d_in[1];         // [32, 2048, 16, 32]
    float* out = (float*)d_out;                     // [64, 32, 32]

    cudaFuncSetAttribute(caps_route_kernel,
                         cudaFuncAttributeMaxDynamicSharedMemorySize, SMEM_BYTES);

    dim3 grid(BATCH * NCAPS);   // bid = c*64 + b  (same-c CTAs co-resident for L2 W reuse)
    caps_route_kernel<<<grid, THREADS, SMEM_BYTES>>>(x, W, out);
}

// round 3
// speedup vs baseline: 3.3333x; 1.4595x over previous
#include <cuda_runtime.h>
#include <cstddef>

#define BATCH   64
#define NCAPS   32
#define NROUTES 2048
#define INDIM   16
#define OUTDIM  32
#define NITERS  3
#define THREADS 512

// SMEM layout (floats):
//   sp[1024][33]   : priors for one half of the routes (33-stride pad -> conflict-free)
//   Vsh[32], sred[32], wred[32], wvec[16*32], scal[8]
#define SP_STRIDE 33
#define OFF_SP    0
#define OFF_VSH   (1024 * SP_STRIDE)
#define OFF_SRED  (OFF_VSH + 32)
#define OFF_WRED  (OFF_SRED + 32)
#define OFF_WVEC  (OFF_WRED + 32)
#define OFF_SCAL  (OFF_WVEC + 16 * 32)
#define SMEM_FLOATS (OFF_SCAL + 8)
#define SMEM_BYTES  (SMEM_FLOATS * 4)

// Quad-route warp scheme: lane l -> route (r4 + l/8), output cols 4*(l%8)..+3.
// Every W load is a coalesced LDG.128 (4 lines per instruction); each lane
// accumulates its 4 columns over all 16 i's privately (no reduction).
__device__ __forceinline__ void quad_routes(const float* __restrict__ x,
                                            const float* __restrict__ W,
                                            int b, int c, int r4,
                                            int rsub, int c4,
                                            float acc[4])
{
    const int r = r4 + rsub;
    const float4* xr = reinterpret_cast<const float4*>(x + ((size_t)b * NROUTES + r) * INDIM);
    const float4* wr = reinterpret_cast<const float4*>(
        W + ((size_t)c * NROUTES + r) * (INDIM * OUTDIM)) + c4;  // stride per i: 8 float4

    float4 xq0 = __ldg(xr + 0);
    float4 xq1 = __ldg(xr + 1);
    float4 xq2 = __ldg(xr + 2);
    float4 xq3 = __ldg(xr + 3);
    float xs[INDIM] = { xq0.x, xq0.y, xq0.z, xq0.w,
                        xq1.x, xq1.y, xq1.z, xq1.w,
                        xq2.x, xq2.y, xq2.z, xq2.w,
                        xq3.x, xq3.y, xq3.z, xq3.w };

    acc[0] = acc[1] = acc[2] = acc[3] = 0.f;

#pragma unroll
    for (int g = 0; g < 4; g++) {
        float4 w0 = __ldg(wr + (g * 4 + 0) * 8);
        float4 w1 = __ldg(wr + (g * 4 + 1) * 8);
        float4 w2 = __ldg(wr + (g * 4 + 2) * 8);
        float4 w3 = __ldg(wr + (g * 4 + 3) * 8);
        float x0 = xs[g * 4 + 0], x1 = xs[g * 4 + 1];
        float x2 = xs[g * 4 + 2], x3 = xs[g * 4 + 3];
        acc[0] = fmaf(x0, w0.x, acc[0]); acc[1] = fmaf(x0, w0.y, acc[1]);
        acc[2] = fmaf(x0, w0.z, acc[2]); acc[3] = fmaf(x0, w0.w, acc[3]);
        acc[0] = fmaf(x1, w1.x, acc[0]); acc[1] = fmaf(x1, w1.y, acc[1]);
        acc[2] = fmaf(x1, w1.z, acc[2]); acc[3] = fmaf(x1, w1.w, acc[3]);
        acc[0] = fmaf(x2, w2.x, acc[0]); acc[1] = fmaf(x2, w2.y, acc[1]);
        acc[2] = fmaf(x2, w2.z, acc[2]); acc[3] = fmaf(x2, w2.w, acc[3]);
        acc[0] = fmaf(x3, w3.x, acc[0]); acc[1] = fmaf(x3, w3.y, acc[1]);
        acc[2] = fmaf(x3, w3.z, acc[2]); acc[3] = fmaf(x3, w3.w, acc[3]);
    }
}

__global__ void __launch_bounds__(THREADS, 1)
caps_route_kernel(const float* __restrict__ x,
                  const float* __restrict__ W,
                  float* __restrict__ out)
{
    extern __shared__ float sm[];
    float* sp   = sm + OFF_SP;
    float* Vsh  = sm + OFF_VSH;
    float* sred = sm + OFF_SRED;
    float* wred = sm + OFF_WRED;
    float* wvec = sm + OFF_WVEC;
    float* scal = sm + OFF_SCAL;

    const int t    = threadIdx.x;
    const int lane = t & 31;
    const int wid  = t >> 5;
    const int rsub = lane >> 3;   // 0..3 : route within quad
    const int c4   = lane & 7;    // 0..7 : float4 column group
    const int b    = blockIdx.x & (BATCH - 1);
    const int c    = blockIdx.x >> 6;

    if (t < 32) Vsh[t] = 0.f;

    // ---------------- Phase 1a: routes 0..1023 (warp w -> 16 quads) ----------------
    {
        const int base = wid * 64;
#pragma unroll 2
        for (int j = 0; j < 64; j += 4) {
            float acc[4];
            quad_routes(x, W, b, c, base + j, rsub, c4, acc);
            float* row = sp + (size_t)(base + j + rsub) * SP_STRIDE + c4 * 4;
            row[0] = acc[0]; row[1] = acc[1]; row[2] = acc[2]; row[3] = acc[3];
        }
    }
    __syncthreads();

    // Each thread pulls its two register rows (routes t and t+512) out of SMEM.
    float accA[OUTDIM], accB[OUTDIM];
    {
        const float* rA = sp + (size_t)t * SP_STRIDE;
        const float* rB = sp + (size_t)(512 + t) * SP_STRIDE;
#pragma unroll
        for (int o = 0; o < OUTDIM; o++) { accA[o] = rA[o]; accB[o] = rB[o]; }
    }
    __syncthreads();

    // ---------------- Phase 1b: routes 1024..2047 overwrite SMEM ----------------
    {
        const int base = wid * 64;
#pragma unroll 2
        for (int j = 0; j < 64; j += 4) {
            float acc[4];
            quad_routes(x, W, b, c, 1024 + base + j, rsub, c4, acc);
            float* row = sp + (size_t)(base + j + rsub) * SP_STRIDE + c4 * 4;
            row[0] = acc[0]; row[1] = acc[1]; row[2] = acc[2]; row[3] = acc[3];
        }
    }
    __syncthreads();

    const float* rowC = sp + (size_t)t * SP_STRIDE;          // route 1024+t
    const float* rowD = sp + (size_t)(512 + t) * SP_STRIDE;  // route 1536+t

    // ---------------- Phase 2: dynamic routing (B_k[n] == p_n . sum_j v_j) ----------------
    for (int it = 0; it < NITERS; it++) {
        float p0, p1, p2, p3;
        if (it == 0) {
            p0 = p1 = p2 = p3 = 1.0f / (float)NROUTES;
        } else {
            float l0 = 0.f, l1 = 0.f, l2 = 0.f, l3 = 0.f;
#pragma unroll
            for (int o = 0; o < OUTDIM; o++) {
                float v = Vsh[o];
                l0 += accA[o] * v;
                l1 += accB[o] * v;
                l2 += rowC[o] * v;
                l3 += rowD[o] * v;
            }
            float m = fmaxf(fmaxf(l0, l1), fmaxf(l2, l3));
#pragma unroll
            for (int s = 16; s; s >>= 1) m = fmaxf(m, __shfl_xor_sync(0xffffffffu, m, s));
            if (lane == 0) wred[wid] = m;
            __syncthreads();
            if (wid == 0) {
                float mm = (lane < 16) ? wred[lane] : -3.402823e38f;
#pragma unroll
                for (int s = 16; s; s >>= 1) mm = fmaxf(mm, __shfl_xor_sync(0xffffffffu, mm, s));
                if (lane == 0) scal[0] = mm;
            }
            __syncthreads();
            const float bmax = scal[0];

            float e0 = __expf(l0 - bmax);
            float e1 = __expf(l1 - bmax);
            float e2 = __expf(l2 - bmax);
            float e3 = __expf(l3 - bmax);
            float zs = e0 + e1 + e2 + e3;
#pragma unroll
            for (int s = 16; s; s >>= 1) zs += __shfl_xor_sync(0xffffffffu, zs, s);
            if (lane == 0) wred[wid] = zs;
            __syncthreads();
            if (wid == 0) {
                float zz = (lane < 16) ? wred[lane] : 0.f;
#pragma unroll
                for (int s = 16; s; s >>= 1) zz += __shfl_xor_sync(0xffffffffu, zz, s);
                if (lane == 0) scal[1] = zz;
            }
            __syncthreads();
            const float invZ = 1.0f / scal[1];
            p0 = e0 * invZ; p1 = e1 * invZ; p2 = e2 * invZ; p3 = e3 * invZ;
        }

        // s = sum_n probs_n * p_n  (deterministic tree reduction)
        float ps[OUTDIM];
#pragma unroll
        for (int o = 0; o < OUTDIM; o++)
            ps[o] = p0 * accA[o] + p1 * accB[o] + p2 * rowC[o] + p3 * rowD[o];
#pragma unroll
        for (int s = 16; s; s >>= 1) {
#pragma unroll
            for (int o = 0; o < OUTDIM; o++)
                ps[o] += __shfl_xor_sync(0xffffffffu, ps[o], s);
        }
        if (lane == 0) {
#pragma unroll
            for (int o = 0; o < OUTDIM; o++) wvec[wid * 32 + o] = ps[o];
        }
        __syncthreads();
        if (t < 32) {
            float sv = 0.f;
#pragma unroll
            for (int w = 0; w < 16; w++) sv += wvec[w * 32 + t];
            sred[t] = sv;
        }
        __syncthreads();

        if (t < 32) {
            float nr = 0.f;
#pragma unroll
            for (int o = 0; o < OUTDIM; o++) { float sv = sred[o]; nr += sv * sv; }
            float scale = (nr / (1.0f + nr)) * rsqrtf(nr);
            float v = scale * sred[t];
            Vsh[t] += v;
            if (it == NITERS - 1)
                out[((size_t)b * NCAPS + c) * OUTDIM + t] = v;
        }
        __syncthreads();
    }
}

extern "C" void kernel_launch(void* const* d_in, const int* in_sizes, int n_in,
                              void* d_out, int out_size)
{
    const float* x = (const float*)d_in[0];         // [64, 2048, 16]
    const float* W = (const float*)d_in[1];         // [32, 2048, 16, 32]
    float* out = (float*)d_out;                     // [64, 32, 32]

    cudaFuncSetAttribute(caps_route_kernel,
                         cudaFuncAttributeMaxDynamicSharedMemorySize, SMEM_BYTES);

    dim3 grid(BATCH * NCAPS);   // bid = c*64 + b  (same-c CTAs co-resident for L2 W reuse)
    caps_route_kernel<<<grid, THREADS, SMEM_BYTES>>>(x, W, out);
}